// round 14
// baseline (speedup 1.0000x reference)
#include <cuda_runtime.h>
#include <cuda_bf16.h>

// PointMatcher: pred (N=1024,20,2) vs gt (M=2048,20,2)
// dist(i,j) = mean_p ||pred[i,p]-gt[j,p]|| ; argmin over j per i.
// Split-plane scheme: gt tiles are transposed into X-plane / Y-plane in smem
// so packed f32x2 math works on natural LDS.64 pairs (no pack MOVs).
// Quad-split-P (pq owns points {4pq..4pq+3} pairs + single {16+pq}).
// 1024-thread blocks, <=32 regs, 2 CTAs/SM. TMA bulk -> staging (double) ->
// transposed planes (double).
// Outputs concatenated in d_out (float32):
//   [0..N*40) matched gt rows | [N*40..N*41) confidence | [N*41..N*42) indices

#define BI      4
#define TJ      128                     // gt rows per tile
#define NTILES  16                      // M / TJ
#define P       20
#define ROWF    40
#define THREADS 1024
#define STGF    (TJ * ROWF)             // staging floats per buffer (5120)
#define STGB    (STGF * 4)              // 20480 bytes
#define PROW    22                      // plane row stride (floats), conflict-free
#define PLANEF  (TJ * PROW)             // 2816 floats per plane

// smem float offsets
#define OFF_STG0   0
#define OFF_STG1   (STGF)
#define OFF_X0     (2 * STGF)
#define OFF_Y0     (OFF_X0 + PLANEF)
#define OFF_X1     (OFF_Y0 + PLANEF)
#define OFF_Y1     (OFF_X1 + PLANEF)
#define OFF_END    (OFF_Y1 + PLANEF)    // 21504 floats
#define SMEM_BYTES (OFF_END * 4 + BI * 8 + 2 * 8)

typedef unsigned long long ull;

__device__ __forceinline__ float fsqrt_approx(float x) {
    float r;
    asm("sqrt.approx.f32 %0, %1;" : "=f"(r) : "f"(x));
    return r;
}
__device__ __forceinline__ ull pack2(float a, float b) {
    ull r;
    asm("mov.b64 %0, {%1,%2};" : "=l"(r) : "f"(a), "f"(b));
    return r;
}
// two squared distances from packed x-pair/y-pair vs packed negated pred
__device__ __forceinline__ void pair2_d2(ull xs, ull ys, ull npx, ull npy,
                                         float& q0, float& q1) {
    ull dx, dy, qx, q;
    asm("add.rn.f32x2 %0, %1, %2;" : "=l"(dx) : "l"(xs), "l"(npx));
    asm("add.rn.f32x2 %0, %1, %2;" : "=l"(dy) : "l"(ys), "l"(npy));
    asm("mul.rn.f32x2 %0, %1, %2;" : "=l"(qx) : "l"(dx), "l"(dx));
    asm("fma.rn.f32x2 %0, %1, %2, %3;" : "=l"(q) : "l"(dy), "l"(dy), "l"(qx));
    asm("mov.b64 {%0,%1}, %2;" : "=f"(q0), "=f"(q1) : "l"(q));
}
__device__ __forceinline__ void mbar_init(unsigned mbar, unsigned cnt) {
    asm volatile("mbarrier.init.shared.b64 [%0], %1;" :: "r"(mbar), "r"(cnt) : "memory");
}
__device__ __forceinline__ void mbar_expect_tx(unsigned mbar, unsigned bytes) {
    asm volatile("mbarrier.arrive.expect_tx.shared.b64 _, [%0], %1;"
                 :: "r"(mbar), "r"(bytes) : "memory");
}
__device__ __forceinline__ void bulk_ld(unsigned dst, const void* src,
                                        unsigned bytes, unsigned mbar) {
    asm volatile(
        "cp.async.bulk.shared::cluster.global.mbarrier::complete_tx::bytes "
        "[%0], [%1], %2, [%3];"
        :: "r"(dst), "l"(src), "r"(bytes), "r"(mbar) : "memory");
}
__device__ __forceinline__ void mbar_wait(unsigned mbar, unsigned phase) {
    asm volatile(
        "{\n\t.reg .pred P1;\n\t"
        "W_%=:\n\t"
        "mbarrier.try_wait.parity.acquire.cta.shared::cta.b64 P1, [%0], %1, 0x989680;\n\t"
        "@P1 bra D_%=;\n\t"
        "bra W_%=;\n\t"
        "D_%=:\n\t}"
        :: "r"(mbar), "r"(phase) : "memory");
}

__global__ __launch_bounds__(THREADS, 2)
void pointmatcher_kernel(const float* __restrict__ pred,
                         const float* __restrict__ gt,
                         float* __restrict__ out_mp,
                         float* __restrict__ out_conf,
                         float* __restrict__ out_idx,
                         int N, int M)
{
    extern __shared__ __align__(16) float smem[];
    ull* best = (ull*)(smem + OFF_END);
    unsigned mbar0 = (unsigned)__cvta_generic_to_shared(best + BI);
    unsigned mbar1 = mbar0 + 8;
    unsigned stg_sa[2] = { (unsigned)__cvta_generic_to_shared(smem + OFF_STG0),
                           (unsigned)__cvta_generic_to_shared(smem + OFF_STG1) };

    const int tid = threadIdx.x;
    const int il  = tid & 3;             // pred row within block
    const int pq  = (tid >> 2) & 3;      // point quarter (partners lane^4, ^8)
    const int jl  = tid >> 4;            // 0..63 -> rows jl, jl+64
    const int i   = blockIdx.x * BI + il;

    if (tid < BI) best[tid] = ~0ull;
    if (tid == 0) { mbar_init(mbar0, 1); mbar_init(mbar1, 1); }

    // Negated pred, pq quarter: pairs A={4pq,4pq+1}, B={4pq+2,4pq+3}, C=16+pq
    ull npxA, npyA, npxB, npyB;
    float npxC, npyC;
    {
        const float2* p2 = (const float2*)(pred + (size_t)i * ROWF);
        float2 a0 = p2[4 * pq], a1 = p2[4 * pq + 1];
        float2 b0 = p2[4 * pq + 2], b1 = p2[4 * pq + 3];
        float2 c  = p2[16 + pq];
        npxA = pack2(-a0.x, -a1.x);  npyA = pack2(-a0.y, -a1.y);
        npxB = pack2(-b0.x, -b1.x);  npyB = pack2(-b0.y, -b1.y);
        npxC = -c.x;                 npyC = -c.y;
    }

    __syncthreads();                     // mbarrier init + best[] visible
    if (tid == 0) {                      // prefetch staging tile 0
        mbar_expect_tx(mbar0, STGB);
        bulk_ld(stg_sa[0], gt, STGB, mbar0);
    }

    float minv = 3.402823466e+38f;       // min of SUM over P (mean deferred)
    int   minj = 0;

    #pragma unroll 2
    for (int t = 0; t < NTILES; t++) {
        const int b = t & 1;
        mbar_wait(b ? mbar1 : mbar0, (t >> 1) & 1);   // staging t landed

        if (tid == 0 && t + 1 < NTILES) {             // start staging t+1
            unsigned mbn = ((t + 1) & 1) ? mbar1 : mbar0;
            mbar_expect_tx(mbn, STGB);
            bulk_ld(stg_sa[(t + 1) & 1],
                    gt + (size_t)(t + 1) * STGF, STGB, mbn);
        }

        // Transpose staging -> X/Y planes (this tile's buffers).
        {
            const float* stg = smem + (b ? OFF_STG1 : OFF_STG0);
            float* xp = smem + (b ? OFF_X1 : OFF_X0);
            float* yp = smem + (b ? OFF_Y1 : OFF_Y0);
            for (int f = tid; f < STGF / 4; f += THREADS) {   // 1280 float4s
                float4 v = *(const float4*)(stg + f * 4);
                int r  = f / 10;
                int k4 = f - r * 10;
                *(float2*)(xp + r * PROW + 2 * k4) = make_float2(v.x, v.z);
                *(float2*)(yp + r * PROW + 2 * k4) = make_float2(v.y, v.w);
            }
        }
        __syncthreads();                 // planes ready for everyone

        const float* xb = smem + (b ? OFF_X1 : OFF_X0);
        const float* yb = smem + (b ? OFF_Y1 : OFF_Y0);
        float s0 = 0.f, s1 = 0.f;

        #pragma unroll
        for (int r = 0; r < 2; r++) {    // rows jl, jl+64
            const float* xr = xb + (jl + 64 * r) * PROW;
            const float* yr = yb + (jl + 64 * r) * PROW;
            float q0, q1, acc = 0.f;
            // pair A: points 4pq, 4pq+1
            pair2_d2(*(const ull*)(xr + 4 * pq), *(const ull*)(yr + 4 * pq),
                     npxA, npyA, q0, q1);
            acc += fsqrt_approx(q0);
            acc += fsqrt_approx(q1);
            // pair B: points 4pq+2, 4pq+3
            pair2_d2(*(const ull*)(xr + 4 * pq + 2), *(const ull*)(yr + 4 * pq + 2),
                     npxB, npyB, q0, q1);
            acc += fsqrt_approx(q0);
            acc += fsqrt_approx(q1);
            // single C: point 16+pq
            {
                float dx = xr[16 + pq] + npxC;
                float dy = yr[16 + pq] + npyC;
                acc += fsqrt_approx(fmaf(dx, dx, dy * dy));
            }
            if (r == 0) s0 = acc; else s1 = acc;
        }

        // Butterfly-combine the 4 point-quarters (same il, jl).
        s0 += __shfl_xor_sync(0xffffffffu, s0, 4);
        s0 += __shfl_xor_sync(0xffffffffu, s0, 8);
        s1 += __shfl_xor_sync(0xffffffffu, s1, 4);
        s1 += __shfl_xor_sync(0xffffffffu, s1, 8);

        int jb = t * TJ + jl;
        if (s0 < minv) { minv = s0; minj = jb;      }  // ascending j order:
        if (s1 < minv) { minv = s1; minj = jb + 64; }  // '<' keeps first tie
    }

    // Block argmin: packed (dist_bits, j); min == (min dist, then min j).
    if (pq == 0) {
        ull key = ((ull)__float_as_uint(minv) << 32) | (unsigned)minj;
        atomicMin(&best[il], key);
    }
    __syncthreads();

    if (tid < BI) {
        ull b = best[tid];
        int j = (int)(unsigned)b;
        float md = __uint_as_float((unsigned)(b >> 32)) * (1.0f / (float)P);
        int row  = blockIdx.x * BI + tid;
        out_conf[row] = (md > 2.0f) ? 0.0f : expf(-md);
        out_idx[row]  = (float)j;
    }
    if (tid < BI * ROWF) {
        int ilg = tid / ROWF;
        int k   = tid - ilg * ROWF;
        int j   = (int)(unsigned)best[ilg];
        out_mp[(blockIdx.x * BI + ilg) * ROWF + k] = gt[(size_t)j * ROWF + k];
    }
}

extern "C" void kernel_launch(void* const* d_in, const int* in_sizes, int n_in,
                              void* d_out, int out_size)
{
    const float* pred = (const float*)d_in[0];
    const float* gt   = (const float*)d_in[1];
    float* out        = (float*)d_out;

    int N = in_sizes[0] / ROWF;   // 1024
    int M = in_sizes[1] / ROWF;   // 2048

    float* out_mp   = out;
    float* out_conf = out + (size_t)N * ROWF;
    float* out_idx  = out + (size_t)N * ROWF + N;

    static bool attr_set = false;  // host-side only; not in the captured graph
    if (!attr_set) {
        cudaFuncSetAttribute(pointmatcher_kernel,
                             cudaFuncAttributeMaxDynamicSharedMemorySize,
                             SMEM_BYTES);
        attr_set = true;
    }

    pointmatcher_kernel<<<N / BI, THREADS, SMEM_BYTES>>>(
        pred, gt, out_mp, out_conf, out_idx, N, M);
}

// round 15
// speedup vs baseline: 1.5130x; 1.5130x over previous
#include <cuda_runtime.h>
#include <cuda_bf16.h>

// PointMatcher: pred (N=1024,20,2) vs gt (M=2048,20,2)
// dist(i,j) = mean_p ||pred[i,p]-gt[j,p]|| ; argmin over j per i.
// Quad-split-P: pq owns points {4pq..4pq+3} (two LDS.128) + {16+pq} (LDS.64),
// scalar f32 math (no pack MOVs). 4 threads (lane^4, lane^8 butterflies)
// cover the 20 points; each thread does 4 gt rows per tile.
// 1024-thread blocks, <=32 regs, 2 CTAs/SM. TMA bulk double-buffered tiles.
// Outputs concatenated in d_out (float32):
//   [0..N*40) matched gt rows | [N*40..N*41) confidence | [N*41..N*42) indices

#define BI      4
#define TJ      256
#define P       20
#define ROWF    40
#define THREADS 1024
#define NTILES  8                           // M/TJ
#define TILEF   (TJ * ROWF)                 // 10240 floats
#define TILEB   (TILEF * 4)                 // 40960 bytes
#define SMEM_BYTES (2*TILEB + BI*8 + 2*8)

typedef unsigned long long ull;

__device__ __forceinline__ float fsqrt_approx(float x) {
    float r;
    asm("sqrt.approx.f32 %0, %1;" : "=f"(r) : "f"(x));
    return r;
}
__device__ __forceinline__ void mbar_init(unsigned mbar, unsigned cnt) {
    asm volatile("mbarrier.init.shared.b64 [%0], %1;" :: "r"(mbar), "r"(cnt) : "memory");
}
__device__ __forceinline__ void mbar_expect_tx(unsigned mbar, unsigned bytes) {
    asm volatile("mbarrier.arrive.expect_tx.shared.b64 _, [%0], %1;"
                 :: "r"(mbar), "r"(bytes) : "memory");
}
__device__ __forceinline__ void bulk_ld(unsigned dst, const void* src,
                                        unsigned bytes, unsigned mbar) {
    asm volatile(
        "cp.async.bulk.shared::cluster.global.mbarrier::complete_tx::bytes "
        "[%0], [%1], %2, [%3];"
        :: "r"(dst), "l"(src), "r"(bytes), "r"(mbar) : "memory");
}
__device__ __forceinline__ void mbar_wait(unsigned mbar, unsigned phase) {
    asm volatile(
        "{\n\t.reg .pred P1;\n\t"
        "W_%=:\n\t"
        "mbarrier.try_wait.parity.acquire.cta.shared::cta.b64 P1, [%0], %1, 0x989680;\n\t"
        "@P1 bra D_%=;\n\t"
        "bra W_%=;\n\t"
        "D_%=:\n\t}"
        :: "r"(mbar), "r"(phase) : "memory");
}

__global__ __launch_bounds__(THREADS, 2)
void pointmatcher_kernel(const float* __restrict__ pred,
                         const float* __restrict__ gt,
                         float* __restrict__ out_mp,
                         float* __restrict__ out_conf,
                         float* __restrict__ out_idx,
                         int N, int M)
{
    extern __shared__ __align__(16) float smem[];
    float* buf0 = smem;
    float* buf1 = smem + TILEF;
    ull*   best = (ull*)(smem + 2 * TILEF);
    unsigned mbar0 = (unsigned)__cvta_generic_to_shared(best + BI);
    unsigned mbar1 = mbar0 + 8;

    const int tid = threadIdx.x;
    const int il  = tid & 3;             // pred row within block
    const int pq  = (tid >> 2) & 3;      // point quarter (partners lane^4, ^8)
    const int jl  = tid >> 4;            // 0..63 -> rows jl+{0,64,128,192}
    const int i   = blockIdx.x * BI + il;

    if (tid < BI) best[tid] = ~0ull;
    if (tid == 0) { mbar_init(mbar0, 1); mbar_init(mbar1, 1); }

    // Pred points owned by this pq: {4pq..4pq+3} and {16+pq}. Plain scalars.
    float px0, py0, px1, py1, px2, py2, px3, py3, px4, py4;
    {
        const float2* p2 = (const float2*)(pred + (size_t)i * ROWF);
        float2 v;
        v = p2[4 * pq];     px0 = v.x; py0 = v.y;
        v = p2[4 * pq + 1]; px1 = v.x; py1 = v.y;
        v = p2[4 * pq + 2]; px2 = v.x; py2 = v.y;
        v = p2[4 * pq + 3]; px3 = v.x; py3 = v.y;
        v = p2[16 + pq];    px4 = v.x; py4 = v.y;
    }

    __syncthreads();                     // mbarrier init + best[] visible
    if (tid == 0) {                      // prefetch tile 0: ONE bulk copy
        mbar_expect_tx(mbar0, TILEB);
        bulk_ld((unsigned)__cvta_generic_to_shared(buf0), gt, TILEB, mbar0);
    }

    float minv = 3.402823466e+38f;       // min of SUM over P (mean deferred)
    int   minj = 0;

    for (int t = 0; t < NTILES; t++) {
        unsigned mb = (t & 1) ? mbar1 : mbar0;
        mbar_wait(mb, (t >> 1) & 1);     // tile t landed
        __syncthreads();                 // all threads done with other buf

        if (tid == 0 && t + 1 < NTILES) {
            unsigned mbn = ((t + 1) & 1) ? mbar1 : mbar0;
            float* dst = ((t + 1) & 1) ? buf1 : buf0;
            mbar_expect_tx(mbn, TILEB);
            bulk_ld((unsigned)__cvta_generic_to_shared(dst),
                    gt + (size_t)(t + 1) * TILEF, TILEB, mbn);
        }

        const float* tb = (t & 1) ? buf1 : buf0;
        const float* base = tb + jl * ROWF;
        float s0, s1, s2, s3;

        #pragma unroll
        for (int r = 0; r < 4; r++) {    // rows jl + 64*r
            const float* rb = base + r * 64 * ROWF;
            // points 4pq..4pq+3 as two LDS.128, point 16+pq as LDS.64
            float4 a = *(const float4*)(rb + 8 * pq);       // {x,y,x,y} pts 0,1
            float4 b = *(const float4*)(rb + 8 * pq + 4);   // pts 2,3
            float2 c = *(const float2*)(rb + 32 + 2 * pq);  // pt 4
            float dx, dy, acc;
            dx = a.x - px0; dy = a.y - py0;
            acc  = fsqrt_approx(fmaf(dx, dx, dy * dy));
            dx = a.z - px1; dy = a.w - py1;
            acc += fsqrt_approx(fmaf(dx, dx, dy * dy));
            dx = b.x - px2; dy = b.y - py2;
            acc += fsqrt_approx(fmaf(dx, dx, dy * dy));
            dx = b.z - px3; dy = b.w - py3;
            acc += fsqrt_approx(fmaf(dx, dx, dy * dy));
            dx = c.x - px4; dy = c.y - py4;
            acc += fsqrt_approx(fmaf(dx, dx, dy * dy));
            if (r == 0) s0 = acc;
            else if (r == 1) s1 = acc;
            else if (r == 2) s2 = acc;
            else s3 = acc;
        }

        // Butterfly-combine the 4 point-quarters (same il, jl).
        s0 += __shfl_xor_sync(0xffffffffu, s0, 4);
        s0 += __shfl_xor_sync(0xffffffffu, s0, 8);
        s1 += __shfl_xor_sync(0xffffffffu, s1, 4);
        s1 += __shfl_xor_sync(0xffffffffu, s1, 8);
        s2 += __shfl_xor_sync(0xffffffffu, s2, 4);
        s2 += __shfl_xor_sync(0xffffffffu, s2, 8);
        s3 += __shfl_xor_sync(0xffffffffu, s3, 4);
        s3 += __shfl_xor_sync(0xffffffffu, s3, 8);

        int jb = t * TJ + jl;
        if (s0 < minv) { minv = s0; minj = jb;       }  // ascending j order:
        if (s1 < minv) { minv = s1; minj = jb + 64;  }  // strict '<' keeps
        if (s2 < minv) { minv = s2; minj = jb + 128; }  // first occurrence
        if (s3 < minv) { minv = s3; minj = jb + 192; }
    }

    // Block argmin: packed (dist_bits, j); min == (min dist, then min j).
    // Only pq==0 issues (all quarters hold identical totals after shfl).
    if (pq == 0) {
        ull key = ((ull)__float_as_uint(minv) << 32) | (unsigned)minj;
        atomicMin(&best[il], key);
    }
    __syncthreads();

    if (tid < BI) {
        ull b = best[tid];
        int j = (int)(unsigned)b;
        float md = __uint_as_float((unsigned)(b >> 32)) * (1.0f / (float)P);
        int row  = blockIdx.x * BI + tid;
        out_conf[row] = (md > 2.0f) ? 0.0f : expf(-md);
        out_idx[row]  = (float)j;
    }
    if (tid < BI * ROWF) {
        int ilg = tid / ROWF;
        int k   = tid - ilg * ROWF;
        int j   = (int)(unsigned)best[ilg];
        out_mp[(blockIdx.x * BI + ilg) * ROWF + k] = gt[(size_t)j * ROWF + k];
    }
}

extern "C" void kernel_launch(void* const* d_in, const int* in_sizes, int n_in,
                              void* d_out, int out_size)
{
    const float* pred = (const float*)d_in[0];
    const float* gt   = (const float*)d_in[1];
    float* out        = (float*)d_out;

    int N = in_sizes[0] / ROWF;   // 1024
    int M = in_sizes[1] / ROWF;   // 2048

    float* out_mp   = out;
    float* out_conf = out + (size_t)N * ROWF;
    float* out_idx  = out + (size_t)N * ROWF + N;

    static bool attr_set = false;  // host-side only; not in the captured graph
    if (!attr_set) {
        cudaFuncSetAttribute(pointmatcher_kernel,
                             cudaFuncAttributeMaxDynamicSharedMemorySize,
                             SMEM_BYTES);
        attr_set = true;
    }

    pointmatcher_kernel<<<N / BI, THREADS, SMEM_BYTES>>>(
        pred, gt, out_mp, out_conf, out_idx, N, M);
}